// round 12
// baseline (speedup 1.0000x reference)
#include <cuda_runtime.h>
#include <cuda_fp16.h>
#include <cstdint>

// ---------------- problem constants ----------------
#define NF_DIM 8192
#define NX_DIM 2048
#define M_DIM  8192
#define BK     64
#define NITER  (NX_DIM / BK)      // 32
#define NSTAGE 3
#define STAGE_BYTES 32768         // A 16K | B 16K
#define SMEM_BYTES (NSTAGE * STAGE_BYTES + 1024)

// ---------------- scratch (device globals; no cudaMalloc allowed) ----------------
static __device__ __align__(256) __half g_A[(size_t)M_DIM * NX_DIM];   // x as fp16
static __device__ __align__(256) __half g_B[(size_t)NF_DIM * NX_DIM];  // s*(q-z) as fp16

// ---------------- helpers ----------------
static __device__ __forceinline__ uint32_t smem_u32(const void* p) {
    uint32_t a;
    asm("{ .reg .u64 t; cvta.to.shared.u64 t, %1; cvt.u32.u64 %0, t; }" : "=r"(a) : "l"(p));
    return a;
}
#define SWZ(o) ((o) ^ ((((uint32_t)(o)) >> 3) & 0x70u))

static __device__ __forceinline__ void cpasync16(uint32_t s, const void* g) {
    asm volatile("cp.async.cg.shared.global [%0], [%1], 16;" :: "r"(s), "l"(g));
}
static __device__ __forceinline__ void cp_commit() {
    asm volatile("cp.async.commit_group;" ::: "memory");
}
static __device__ __forceinline__ void cp_wait2() {
    asm volatile("cp.async.wait_group 2;" ::: "memory");
}
static __device__ __forceinline__ void ldm4(uint32_t* r, uint32_t addr) {
    asm volatile("ldmatrix.sync.aligned.m8n8.x4.shared.b16 {%0,%1,%2,%3}, [%4];"
                 : "=r"(r[0]), "=r"(r[1]), "=r"(r[2]), "=r"(r[3]) : "r"(addr));
}
static __device__ __forceinline__ void mma16816(float* c, const uint32_t* a, uint32_t b0, uint32_t b1) {
    asm volatile(
        "mma.sync.aligned.m16n8k16.row.col.f32.f16.f16.f32 "
        "{%0,%1,%2,%3}, {%4,%5,%6,%7}, {%8,%9}, {%0,%1,%2,%3};"
        : "+f"(c[0]), "+f"(c[1]), "+f"(c[2]), "+f"(c[3])
        : "r"(a[0]), "r"(a[1]), "r"(a[2]), "r"(a[3]), "r"(b0), "r"(b1));
}

// ---------------- fused prep: blocks [0,8192) convert x, [8192,16384) dequant W ----------------
__global__ __launch_bounds__(256) void prep_kernel(const float* __restrict__ x,
                                                   const int* __restrict__ packed,
                                                   const float* __restrict__ scales,
                                                   const int* __restrict__ zeros) {
    if (blockIdx.x < 8192) {
        // ---- x -> fp16 ----
        size_t i = ((size_t)blockIdx.x * blockDim.x + threadIdx.x) * 8;
        float4 u0 = *(const float4*)(x + i);
        float4 u1 = *(const float4*)(x + i + 4);
        __half2 h0 = __float22half2_rn(make_float2(u0.x, u0.y));
        __half2 h1 = __float22half2_rn(make_float2(u0.z, u0.w));
        __half2 h2 = __float22half2_rn(make_float2(u1.x, u1.y));
        __half2 h3 = __float22half2_rn(make_float2(u1.z, u1.w));
        uint4 o;
        o.x = *(uint32_t*)&h0; o.y = *(uint32_t*)&h1;
        o.z = *(uint32_t*)&h2; o.w = *(uint32_t*)&h3;
        *(uint4*)(g_A + i) = o;
    } else {
        // ---- W = s*(q-z) -> fp16 ----
        // packed[n][j]: one byte per int32, low nibble = weight 2j, high = 2j+1.
        size_t i = ((size_t)(blockIdx.x - 8192) * blockDim.x + threadIdx.x);  // over NF*1024/4
        int4 p = ((const int4*)packed)[i];
        int n  = (int)((i * 4) >> 10);
        int j0 = (int)((i * 4) & 1023);
        int g  = j0 >> 5;
        float s  = scales[n * 32 + g];
        float zs = (float)zeros[n * 32 + g] * s;

        int pp[4] = {p.x, p.y, p.z, p.w};
        uint32_t w[4];
        #pragma unroll
        for (int q = 0; q < 4; q++) {
            float f0 = (float)(pp[q] & 15) * s - zs;
            float f1 = (float)((pp[q] >> 4) & 15) * s - zs;
            __half2 hh = __float22half2_rn(make_float2(f0, f1));
            w[q] = *(uint32_t*)&hh;
        }
        uint4 o; o.x = w[0]; o.y = w[1]; o.z = w[2]; o.w = w[3];
        *(uint4*)(g_B + (size_t)n * NX_DIM + (size_t)j0 * 2) = o;
    }
}

// ---------------- GEMM: D = A @ B^T + bias, single-pass fp16 HMMA ----------------
// 256 threads = 8 warps, warp grid 2(M) x 4(N), warp tile 64x32. 2 CTAs/SM.
// 3-stage cp.async pipeline, R7 ordering (issue loads BEFORE the wait):
//   loop j: load(j+2) ; wait_group 2 (stage j landed) ; sync ; compute j ; sync
__global__ __launch_bounds__(256, 2)
void gemm_kernel(float* __restrict__ out, const float* __restrict__ bias) {
    extern __shared__ char smem[];
    const uint32_t sb = smem_u32(smem);
    const uint32_t TILE0 = (sb + 1023) & ~1023u;

    const int tid = threadIdx.x;
    const int wid = tid >> 5, lid = tid & 31;
    const int warp_m = wid & 1;
    const int warp_n = wid >> 1;

    const int t  = blockIdx.x;
    const int bm = ((t >> 9) << 3) | (t & 7);   // 8-wide M supertiles: B panel L2-resident
    const int bn = (t >> 3) & 63;

    const char* gA = (const char*)(g_A + (size_t)bm * 128 * NX_DIM);
    const char* gB = (const char*)(g_B + (size_t)bn * 128 * NX_DIM);

    // stage loader: A tile (128 rows x 64 halves = 16KB) + B tile
    auto load_stage = [&](int j, int slot) {
        const uint32_t s0 = TILE0 + slot * STAGE_BYTES;
        #pragma unroll
        for (int i = 0; i < 4; i++) {
            const int c   = tid + i * 256;       // 0..1023: 16B chunk id
            const int row = c >> 3;
            const int seg = c & 7;
            const uint32_t so = SWZ((uint32_t)(row * 128 + seg * 16));
            const size_t go = (size_t)row * (NX_DIM * 2) + (size_t)j * (BK * 2) + seg * 16;
            cpasync16(s0 +         so, gA + go);
            cpasync16(s0 + 16384 + so, gB + go);
        }
        cp_commit();
    };

    float acc[4][4][4];
    #pragma unroll
    for (int a = 0; a < 4; a++)
        #pragma unroll
        for (int b = 0; b < 4; b++)
            #pragma unroll
            for (int c = 0; c < 4; c++) acc[a][b][c] = 0.f;

    // ldmatrix lane addressing (elements)
    const int laneA_row = (lid & 7) + ((lid >> 3) & 1) * 8;
    const int laneA_k8  = ((lid >> 4) & 1) * 8;
    const int laneB_row = (lid & 7) + ((lid >> 4) & 1) * 8;
    const int laneB_k8  = ((lid >> 3) & 1) * 8;

    load_stage(0, 0);
    load_stage(1, 1);

    #pragma unroll 1
    for (int j = 0; j < NITER; j++) {
        if (j + 2 < NITER) load_stage(j + 2, (j + 2) % NSTAGE);
        else cp_commit();               // keep per-thread group accounting symmetric
        cp_wait2();                     // stage j landed (<=2 groups outstanding)
        __syncthreads();

        const uint32_t s0 = TILE0 + (j % NSTAGE) * STAGE_BYTES;
        const uint32_t Ab = s0, Bb = s0 + 16384;

        #pragma unroll
        for (int ks = 0; ks < 4; ks++) {
            uint32_t af[4][4], bf[2][4];
            #pragma unroll
            for (int mt = 0; mt < 4; mt++) {
                const uint32_t off = SWZ((uint32_t)((warp_m * 64 + mt * 16 + laneA_row) * 128
                                                    + (ks * 16 + laneA_k8) * 2));
                ldm4(af[mt], Ab + off);
            }
            #pragma unroll
            for (int h = 0; h < 2; h++) {
                const uint32_t off = SWZ((uint32_t)((warp_n * 32 + h * 16 + laneB_row) * 128
                                                    + (ks * 16 + laneB_k8) * 2));
                ldm4(bf[h], Bb + off);
            }
            #pragma unroll
            for (int mt = 0; mt < 4; mt++)
                #pragma unroll
                for (int nt = 0; nt < 4; nt++) {
                    const uint32_t b0 = bf[nt >> 1][(nt & 1) * 2];
                    const uint32_t b1 = bf[nt >> 1][(nt & 1) * 2 + 1];
                    mma16816(acc[mt][nt], af[mt], b0, b1);
                }
        }
        __syncthreads();
    }

    // ---- epilogue: add bias, store fp32 ----
    const int gm0 = bm * 128 + warp_m * 64 + (lid >> 2);
    const int gn0 = bn * 128 + warp_n * 32 + (lid & 3) * 2;
    #pragma unroll
    for (int nt = 0; nt < 4; nt++) {
        const int gn = gn0 + nt * 8;
        const float2 bv = *(const float2*)(bias + gn);
        #pragma unroll
        for (int mt = 0; mt < 4; mt++) {
            const int gm = gm0 + mt * 16;
            float2 v0, v1;
            v0.x = acc[mt][nt][0] + bv.x;  v0.y = acc[mt][nt][1] + bv.y;
            v1.x = acc[mt][nt][2] + bv.x;  v1.y = acc[mt][nt][3] + bv.y;
            *(float2*)(out + (size_t)gm * NF_DIM + gn)       = v0;
            *(float2*)(out + (size_t)(gm + 8) * NF_DIM + gn) = v1;
        }
    }
}

// ---------------- launch ----------------
extern "C" void kernel_launch(void* const* d_in, const int* in_sizes, int n_in,
                              void* d_out, int out_size) {
    const float* x      = (const float*)d_in[0];
    const int*   packed = (const int*)d_in[1];
    const float* scales = (const float*)d_in[2];
    const int*   zeros  = (const int*)d_in[3];
    const float* bias   = (const float*)d_in[4];
    float*       out    = (float*)d_out;

    cudaFuncSetAttribute(gemm_kernel, cudaFuncAttributeMaxDynamicSharedMemorySize, SMEM_BYTES);

    prep_kernel<<<16384, 256>>>(x, packed, scales, zeros);
    gemm_kernel<<<64 * 64, 256, SMEM_BYTES>>>(out, bias);
}

// round 13
// speedup vs baseline: 1.0483x; 1.0483x over previous
#include <cuda_runtime.h>
#include <cuda_fp16.h>
#include <cstdint>

// ---------------- problem constants ----------------
#define NF_DIM 8192
#define NX_DIM 2048
#define M_DIM  8192
#define BK     64
#define NITER  (NX_DIM / BK)      // 32
#define STAGE_BYTES 32768         // A 16K | B 16K
#define SMEM_BYTES (2 * STAGE_BYTES + 1024)

// ---------------- scratch (device globals; no cudaMalloc allowed) ----------------
static __device__ __align__(256) __half g_A[(size_t)M_DIM * NX_DIM];   // x as fp16
static __device__ __align__(256) __half g_B[(size_t)NF_DIM * NX_DIM];  // s*(q-z) as fp16

// ---------------- helpers ----------------
static __device__ __forceinline__ uint32_t smem_u32(const void* p) {
    uint32_t a;
    asm("{ .reg .u64 t; cvta.to.shared.u64 t, %1; cvt.u32.u64 %0, t; }" : "=r"(a) : "l"(p));
    return a;
}
#define SWZ(o) ((o) ^ ((((uint32_t)(o)) >> 3) & 0x70u))

static __device__ __forceinline__ void cpasync16(uint32_t s, const void* g) {
    asm volatile("cp.async.cg.shared.global [%0], [%1], 16;" :: "r"(s), "l"(g));
}
static __device__ __forceinline__ void cp_commit() {
    asm volatile("cp.async.commit_group;" ::: "memory");
}
static __device__ __forceinline__ void cp_wait1() {
    asm volatile("cp.async.wait_group 1;" ::: "memory");
}
static __device__ __forceinline__ void cp_wait0() {
    asm volatile("cp.async.wait_group 0;" ::: "memory");
}
static __device__ __forceinline__ void ldm4(uint32_t* r, uint32_t addr) {
    asm volatile("ldmatrix.sync.aligned.m8n8.x4.shared.b16 {%0,%1,%2,%3}, [%4];"
                 : "=r"(r[0]), "=r"(r[1]), "=r"(r[2]), "=r"(r[3]) : "r"(addr));
}
static __device__ __forceinline__ void mma16816(float* c, const uint32_t* a, uint32_t b0, uint32_t b1) {
    asm volatile(
        "mma.sync.aligned.m16n8k16.row.col.f32.f16.f16.f32 "
        "{%0,%1,%2,%3}, {%4,%5,%6,%7}, {%8,%9}, {%0,%1,%2,%3};"
        : "+f"(c[0]), "+f"(c[1]), "+f"(c[2]), "+f"(c[3])
        : "r"(a[0]), "r"(a[1]), "r"(a[2]), "r"(a[3]), "r"(b0), "r"(b1));
}

// ---------------- fused prep: blocks [0,8192) convert x, [8192,16384) dequant W ----------------
__global__ __launch_bounds__(256) void prep_kernel(const float* __restrict__ x,
                                                   const int* __restrict__ packed,
                                                   const float* __restrict__ scales,
                                                   const int* __restrict__ zeros) {
    if (blockIdx.x < 8192) {
        // ---- x -> fp16 ----
        size_t i = ((size_t)blockIdx.x * blockDim.x + threadIdx.x) * 8;
        float4 u0 = *(const float4*)(x + i);
        float4 u1 = *(const float4*)(x + i + 4);
        __half2 h0 = __float22half2_rn(make_float2(u0.x, u0.y));
        __half2 h1 = __float22half2_rn(make_float2(u0.z, u0.w));
        __half2 h2 = __float22half2_rn(make_float2(u1.x, u1.y));
        __half2 h3 = __float22half2_rn(make_float2(u1.z, u1.w));
        uint4 o;
        o.x = *(uint32_t*)&h0; o.y = *(uint32_t*)&h1;
        o.z = *(uint32_t*)&h2; o.w = *(uint32_t*)&h3;
        *(uint4*)(g_A + i) = o;
    } else {
        // ---- W = s*(q-z) -> fp16 ----
        size_t i = ((size_t)(blockIdx.x - 8192) * blockDim.x + threadIdx.x);  // over NF*1024/4
        int4 p = ((const int4*)packed)[i];
        int n  = (int)((i * 4) >> 10);
        int j0 = (int)((i * 4) & 1023);
        int g  = j0 >> 5;
        float s  = scales[n * 32 + g];
        float zs = (float)zeros[n * 32 + g] * s;

        int pp[4] = {p.x, p.y, p.z, p.w};
        uint32_t w[4];
        #pragma unroll
        for (int q = 0; q < 4; q++) {
            float f0 = (float)(pp[q] & 15) * s - zs;
            float f1 = (float)((pp[q] >> 4) & 15) * s - zs;
            __half2 hh = __float22half2_rn(make_float2(f0, f1));
            w[q] = *(uint32_t*)&hh;
        }
        uint4 o; o.x = w[0]; o.y = w[1]; o.z = w[2]; o.w = w[3];
        *(uint4*)(g_B + (size_t)n * NX_DIM + (size_t)j0 * 2) = o;
    }
}

// ---------------- GEMM: D = A @ B^T + bias, fp16 HMMA ----------------
// 128 threads = 4 warps, warp grid 2(M) x 2(N), warp tile 64x64. 2 CTAs/SM.
// 2-stage cp.async pipeline, R7 ordering: load(j+1) ; wait1 ; sync ; compute j ; sync.
__global__ __launch_bounds__(128, 2)
void gemm_kernel(float* __restrict__ out, const float* __restrict__ bias) {
    extern __shared__ char smem[];
    const uint32_t sb = smem_u32(smem);
    const uint32_t TILE0 = (sb + 1023) & ~1023u;

    const int tid = threadIdx.x;
    const int wid = tid >> 5, lid = tid & 31;
    const int warp_m = wid & 1;     // 0..1 : 64 rows
    const int warp_n = wid >> 1;    // 0..1 : 64 cols

    const int t  = blockIdx.x;
    const int bm = ((t >> 9) << 3) | (t & 7);   // 8-wide M supertiles: B panel L2-resident
    const int bn = (t >> 3) & 63;

    const char* gA = (const char*)(g_A + (size_t)bm * 128 * NX_DIM);
    const char* gB = (const char*)(g_B + (size_t)bn * 128 * NX_DIM);

    // stage loader: A tile (128 rows x 64 halves = 16KB) + B tile; 128 thr x 8 chunks each
    auto load_stage = [&](int j, int slot) {
        const uint32_t s0 = TILE0 + slot * STAGE_BYTES;
        #pragma unroll
        for (int i = 0; i < 8; i++) {
            const int c   = tid + i * 128;       // 0..1023: 16B chunk id
            const int row = c >> 3;
            const int seg = c & 7;
            const uint32_t so = SWZ((uint32_t)(row * 128 + seg * 16));
            const size_t go = (size_t)row * (NX_DIM * 2) + (size_t)j * (BK * 2) + seg * 16;
            cpasync16(s0 +         so, gA + go);
            cpasync16(s0 + 16384 + so, gB + go);
        }
        cp_commit();
    };

    float acc[4][8][4];
    #pragma unroll
    for (int a = 0; a < 4; a++)
        #pragma unroll
        for (int b = 0; b < 8; b++)
            #pragma unroll
            for (int c = 0; c < 4; c++) acc[a][b][c] = 0.f;

    // ldmatrix lane addressing (elements)
    const int laneA_row = (lid & 7) + ((lid >> 3) & 1) * 8;
    const int laneA_k8  = ((lid >> 4) & 1) * 8;
    const int laneB_row = (lid & 7) + ((lid >> 4) & 1) * 8;
    const int laneB_k8  = ((lid >> 3) & 1) * 8;

    load_stage(0, 0);

    #pragma unroll 1
    for (int j = 0; j < NITER; j++) {
        if (j + 1 < NITER) { load_stage(j + 1, (j + 1) & 1); cp_wait1(); }
        else               { cp_wait0(); }
        __syncthreads();

        const uint32_t s0 = TILE0 + (j & 1) * STAGE_BYTES;
        const uint32_t Ab = s0, Bb = s0 + 16384;

        #pragma unroll
        for (int ks = 0; ks < 4; ks++) {
            uint32_t af[4][4], bf[4][4];
            #pragma unroll
            for (int mt = 0; mt < 4; mt++) {
                const uint32_t off = SWZ((uint32_t)((warp_m * 64 + mt * 16 + laneA_row) * 128
                                                    + (ks * 16 + laneA_k8) * 2));
                ldm4(af[mt], Ab + off);
            }
            #pragma unroll
            for (int h = 0; h < 4; h++) {
                const uint32_t off = SWZ((uint32_t)((warp_n * 64 + h * 16 + laneB_row) * 128
                                                    + (ks * 16 + laneB_k8) * 2));
                ldm4(bf[h], Bb + off);
            }
            #pragma unroll
            for (int mt = 0; mt < 4; mt++)
                #pragma unroll
                for (int nt = 0; nt < 8; nt++) {
                    const uint32_t b0 = bf[nt >> 1][(nt & 1) * 2];
                    const uint32_t b1 = bf[nt >> 1][(nt & 1) * 2 + 1];
                    mma16816(acc[mt][nt], af[mt], b0, b1);
                }
        }
        __syncthreads();
    }

    // ---- epilogue: add bias, store fp32 ----
    const int gm0 = bm * 128 + warp_m * 64 + (lid >> 2);
    const int gn0 = bn * 128 + warp_n * 64 + (lid & 3) * 2;
    #pragma unroll
    for (int nt = 0; nt < 8; nt++) {
        const int gn = gn0 + nt * 8;
        const float2 bv = *(const float2*)(bias + gn);
        #pragma unroll
        for (int mt = 0; mt < 4; mt++) {
            const int gm = gm0 + mt * 16;
            float2 v0, v1;
            v0.x = acc[mt][nt][0] + bv.x;  v0.y = acc[mt][nt][1] + bv.y;
            v1.x = acc[mt][nt][2] + bv.x;  v1.y = acc[mt][nt][3] + bv.y;
            *(float2*)(out + (size_t)gm * NF_DIM + gn)       = v0;
            *(float2*)(out + (size_t)(gm + 8) * NF_DIM + gn) = v1;
        }
    }
}

// ---------------- launch ----------------
extern "C" void kernel_launch(void* const* d_in, const int* in_sizes, int n_in,
                              void* d_out, int out_size) {
    const float* x      = (const float*)d_in[0];
    const int*   packed = (const int*)d_in[1];
    const float* scales = (const float*)d_in[2];
    const int*   zeros  = (const int*)d_in[3];
    const float* bias   = (const float*)d_in[4];
    float*       out    = (float*)d_out;

    cudaFuncSetAttribute(gemm_kernel, cudaFuncAttributeMaxDynamicSharedMemorySize, SMEM_BYTES);

    prep_kernel<<<16384, 256>>>(x, packed, scales, zeros);
    gemm_kernel<<<64 * 64, 128, SMEM_BYTES>>>(out, bias);
}

// round 14
// speedup vs baseline: 1.0970x; 1.0464x over previous
#include <cuda_runtime.h>
#include <cuda_fp16.h>
#include <cstdint>

// ---------------- problem constants ----------------
#define NF_DIM 8192
#define NX_DIM 2048
#define M_DIM  8192
#define BK     64
#define NITER  (NX_DIM / BK)      // 32
#define STAGE_BYTES 32768         // A 16K | B 16K
#define SMEM_BYTES (2 * STAGE_BYTES + 1024)

// ---------------- scratch (device globals; no cudaMalloc allowed) ----------------
static __device__ __align__(256) __half g_A[(size_t)M_DIM * NX_DIM];   // x as fp16
static __device__ __align__(256) __half g_B[(size_t)NF_DIM * NX_DIM];  // s*(q-z) as fp16

// ---------------- helpers ----------------
static __device__ __forceinline__ uint32_t smem_u32(const void* p) {
    uint32_t a;
    asm("{ .reg .u64 t; cvta.to.shared.u64 t, %1; cvt.u32.u64 %0, t; }" : "=r"(a) : "l"(p));
    return a;
}
#define SWZ(o) ((o) ^ ((((uint32_t)(o)) >> 3) & 0x70u))

static __device__ __forceinline__ void cpasync16(uint32_t s, const void* g) {
    asm volatile("cp.async.cg.shared.global [%0], [%1], 16;" :: "r"(s), "l"(g));
}
static __device__ __forceinline__ void cp_commit() {
    asm volatile("cp.async.commit_group;" ::: "memory");
}
static __device__ __forceinline__ void cp_wait1() {
    asm volatile("cp.async.wait_group 1;" ::: "memory");
}
static __device__ __forceinline__ void cp_wait0() {
    asm volatile("cp.async.wait_group 0;" ::: "memory");
}
static __device__ __forceinline__ void ldm4(uint32_t* r, uint32_t addr) {
    asm volatile("ldmatrix.sync.aligned.m8n8.x4.shared.b16 {%0,%1,%2,%3}, [%4];"
                 : "=r"(r[0]), "=r"(r[1]), "=r"(r[2]), "=r"(r[3]) : "r"(addr));
}
static __device__ __forceinline__ void mma16816(float* c, const uint32_t* a, uint32_t b0, uint32_t b1) {
    asm volatile(
        "mma.sync.aligned.m16n8k16.row.col.f32.f16.f16.f32 "
        "{%0,%1,%2,%3}, {%4,%5,%6,%7}, {%8,%9}, {%0,%1,%2,%3};"
        : "+f"(c[0]), "+f"(c[1]), "+f"(c[2]), "+f"(c[3])
        : "r"(a[0]), "r"(a[1]), "r"(a[2]), "r"(a[3]), "r"(b0), "r"(b1));
}

// ---------------- fused prep: blocks [0,8192) convert x, [8192,16384) dequant W ----------------
__global__ __launch_bounds__(256) void prep_kernel(const float* __restrict__ x,
                                                   const int* __restrict__ packed,
                                                   const float* __restrict__ scales,
                                                   const int* __restrict__ zeros) {
    if (blockIdx.x < 8192) {
        // ---- x -> fp16 ----
        size_t i = ((size_t)blockIdx.x * blockDim.x + threadIdx.x) * 8;
        float4 u0 = *(const float4*)(x + i);
        float4 u1 = *(const float4*)(x + i + 4);
        __half2 h0 = __float22half2_rn(make_float2(u0.x, u0.y));
        __half2 h1 = __float22half2_rn(make_float2(u0.z, u0.w));
        __half2 h2 = __float22half2_rn(make_float2(u1.x, u1.y));
        __half2 h3 = __float22half2_rn(make_float2(u1.z, u1.w));
        uint4 o;
        o.x = *(uint32_t*)&h0; o.y = *(uint32_t*)&h1;
        o.z = *(uint32_t*)&h2; o.w = *(uint32_t*)&h3;
        *(uint4*)(g_A + i) = o;
    } else {
        // ---- W = s*(q-z) -> fp16 ----
        // packed[n][j]: one byte per int32, low nibble = weight 2j, high = 2j+1.
        size_t i = ((size_t)(blockIdx.x - 8192) * blockDim.x + threadIdx.x);  // over NF*1024/4
        int4 p = ((const int4*)packed)[i];
        int n  = (int)((i * 4) >> 10);
        int j0 = (int)((i * 4) & 1023);
        int g  = j0 >> 5;
        float s  = scales[n * 32 + g];
        float zs = (float)zeros[n * 32 + g] * s;

        int pp[4] = {p.x, p.y, p.z, p.w};
        uint32_t w[4];
        #pragma unroll
        for (int q = 0; q < 4; q++) {
            float f0 = (float)(pp[q] & 15) * s - zs;
            float f1 = (float)((pp[q] >> 4) & 15) * s - zs;
            __half2 hh = __float22half2_rn(make_float2(f0, f1));
            w[q] = *(uint32_t*)&hh;
        }
        uint4 o; o.x = w[0]; o.y = w[1]; o.z = w[2]; o.w = w[3];
        *(uint4*)(g_B + (size_t)n * NX_DIM + (size_t)j0 * 2) = o;
    }
}

// ---------------- GEMM: D = A @ B^T + bias, single-pass fp16 HMMA ----------------
// 256 threads = 8 warps, warp grid 2(M) x 4(N), warp tile 64x32. 2 CTAs/SM.
// 2-stage pipeline (R7 ordering): load(j+1) ; wait1 ; sync ; compute j ; sync.
__global__ __launch_bounds__(256, 2)
void gemm_kernel(float* __restrict__ out, const float* __restrict__ bias) {
    extern __shared__ char smem[];
    const uint32_t sb = smem_u32(smem);
    const uint32_t TILE0 = (sb + 1023) & ~1023u;

    const int tid = threadIdx.x;
    const int wid = tid >> 5, lid = tid & 31;
    const int warp_m = wid & 1;
    const int warp_n = wid >> 1;

    const int t  = blockIdx.x;
    const int bm = ((t >> 9) << 3) | (t & 7);   // 8-wide M supertiles: B panel L2-resident
    const int bn = (t >> 3) & 63;

    const char* gA = (const char*)(g_A + (size_t)bm * 128 * NX_DIM);
    const char* gB = (const char*)(g_B + (size_t)bn * 128 * NX_DIM);

    // stage loader: A tile (128 rows x 64 halves = 16KB) + B tile
    auto load_stage = [&](int j, int slot) {
        const uint32_t s0 = TILE0 + slot * STAGE_BYTES;
        #pragma unroll
        for (int i = 0; i < 4; i++) {
            const int c   = tid + i * 256;       // 0..1023: 16B chunk id
            const int row = c >> 3;
            const int seg = c & 7;
            const uint32_t so = SWZ((uint32_t)(row * 128 + seg * 16));
            const size_t go = (size_t)row * (NX_DIM * 2) + (size_t)j * (BK * 2) + seg * 16;
            cpasync16(s0 +         so, gA + go);
            cpasync16(s0 + 16384 + so, gB + go);
        }
        cp_commit();
    };

    float acc[4][4][4];
    #pragma unroll
    for (int a = 0; a < 4; a++)
        #pragma unroll
        for (int b = 0; b < 4; b++)
            #pragma unroll
            for (int c = 0; c < 4; c++) acc[a][b][c] = 0.f;

    // ldmatrix lane addressing (elements)
    const int laneA_row = (lid & 7) + ((lid >> 3) & 1) * 8;
    const int laneA_k8  = ((lid >> 4) & 1) * 8;
    const int laneB_row = (lid & 7) + ((lid >> 4) & 1) * 8;
    const int laneB_k8  = ((lid >> 3) & 1) * 8;

    load_stage(0, 0);

    #pragma unroll 1
    for (int j = 0; j < NITER; j++) {
        if (j + 1 < NITER) { load_stage(j + 1, (j + 1) & 1); cp_wait1(); }
        else               { cp_wait0(); }
        __syncthreads();

        const uint32_t s0 = TILE0 + (j & 1) * STAGE_BYTES;
        const uint32_t Ab = s0, Bb = s0 + 16384;

        #pragma unroll
        for (int ks = 0; ks < 4; ks++) {
            uint32_t af[4][4], bf[2][4];
            // issue order: the first MMA's operands (af[0], bf[0], bf[1]) first
            {
                const uint32_t offA0 = SWZ((uint32_t)((warp_m * 64 + laneA_row) * 128
                                                      + (ks * 16 + laneA_k8) * 2));
                ldm4(af[0], Ab + offA0);
            }
            #pragma unroll
            for (int h = 0; h < 2; h++) {
                const uint32_t off = SWZ((uint32_t)((warp_n * 32 + h * 16 + laneB_row) * 128
                                                    + (ks * 16 + laneB_k8) * 2));
                ldm4(bf[h], Bb + off);
            }
            #pragma unroll
            for (int mt = 1; mt < 4; mt++) {
                const uint32_t off = SWZ((uint32_t)((warp_m * 64 + mt * 16 + laneA_row) * 128
                                                    + (ks * 16 + laneA_k8) * 2));
                ldm4(af[mt], Ab + off);
            }
            #pragma unroll
            for (int mt = 0; mt < 4; mt++)
                #pragma unroll
                for (int nt = 0; nt < 4; nt++) {
                    const uint32_t b0 = bf[nt >> 1][(nt & 1) * 2];
                    const uint32_t b1 = bf[nt >> 1][(nt & 1) * 2 + 1];
                    mma16816(acc[mt][nt], af[mt], b0, b1);
                }
        }
        __syncthreads();
    }

    // ---- epilogue: add bias, store fp32 ----
    const int gm0 = bm * 128 + warp_m * 64 + (lid >> 2);
    const int gn0 = bn * 128 + warp_n * 32 + (lid & 3) * 2;
    #pragma unroll
    for (int nt = 0; nt < 4; nt++) {
        const int gn = gn0 + nt * 8;
        const float2 bv = *(const float2*)(bias + gn);
        #pragma unroll
        for (int mt = 0; mt < 4; mt++) {
            const int gm = gm0 + mt * 16;
            float2 v0, v1;
            v0.x = acc[mt][nt][0] + bv.x;  v0.y = acc[mt][nt][1] + bv.y;
            v1.x = acc[mt][nt][2] + bv.x;  v1.y = acc[mt][nt][3] + bv.y;
            *(float2*)(out + (size_t)gm * NF_DIM + gn)       = v0;
            *(float2*)(out + (size_t)(gm + 8) * NF_DIM + gn) = v1;
        }
    }
}

// ---------------- launch ----------------
extern "C" void kernel_launch(void* const* d_in, const int* in_sizes, int n_in,
                              void* d_out, int out_size) {
    const float* x      = (const float*)d_in[0];
    const int*   packed = (const int*)d_in[1];
    const float* scales = (const float*)d_in[2];
    const int*   zeros  = (const int*)d_in[3];
    const float* bias   = (const float*)d_in[4];
    float*       out    = (float*)d_out;

    cudaFuncSetAttribute(gemm_kernel, cudaFuncAttributeMaxDynamicSharedMemorySize, SMEM_BYTES);

    prep_kernel<<<16384, 256>>>(x, packed, scales, zeros);
    gemm_kernel<<<64 * 64, 256, SMEM_BYTES>>>(out, bias);
}

// round 15
// speedup vs baseline: 1.1396x; 1.0388x over previous
#include <cuda_runtime.h>
#include <cuda_fp16.h>
#include <cstdint>

// ---------------- problem constants ----------------
#define NF_DIM 8192
#define NX_DIM 2048
#define M_DIM  8192
#define BK     64
#define NITER  (NX_DIM / BK)      // 32
#define NSTAGE 3
#define STAGE_BYTES 32768         // A 16K | B 16K
#define SMEM_BYTES (NSTAGE * STAGE_BYTES + 1024)

// ---------------- scratch (device globals; no cudaMalloc allowed) ----------------
static __device__ __align__(256) __half g_A[(size_t)M_DIM * NX_DIM];   // x as fp16
static __device__ __align__(256) __half g_B[(size_t)NF_DIM * NX_DIM];  // s*(q-z) as fp16

// ---------------- helpers ----------------
static __device__ __forceinline__ uint32_t smem_u32(const void* p) {
    uint32_t a;
    asm("{ .reg .u64 t; cvta.to.shared.u64 t, %1; cvt.u32.u64 %0, t; }" : "=r"(a) : "l"(p));
    return a;
}
#define SWZ(o) ((o) ^ ((((uint32_t)(o)) >> 3) & 0x70u))

static __device__ __forceinline__ void cpasync16(uint32_t s, const void* g) {
    asm volatile("cp.async.cg.shared.global [%0], [%1], 16;" :: "r"(s), "l"(g));
}
static __device__ __forceinline__ void cp_commit() {
    asm volatile("cp.async.commit_group;" ::: "memory");
}
static __device__ __forceinline__ void cp_wait1() {
    asm volatile("cp.async.wait_group 1;" ::: "memory");
}
static __device__ __forceinline__ void cp_wait0() {
    asm volatile("cp.async.wait_group 0;" ::: "memory");
}
static __device__ __forceinline__ void ldm4(uint32_t* r, uint32_t addr) {
    asm volatile("ldmatrix.sync.aligned.m8n8.x4.shared.b16 {%0,%1,%2,%3}, [%4];"
                 : "=r"(r[0]), "=r"(r[1]), "=r"(r[2]), "=r"(r[3]) : "r"(addr));
}
static __device__ __forceinline__ void mma16816(float* c, const uint32_t* a, uint32_t b0, uint32_t b1) {
    asm volatile(
        "mma.sync.aligned.m16n8k16.row.col.f32.f16.f16.f32 "
        "{%0,%1,%2,%3}, {%4,%5,%6,%7}, {%8,%9}, {%0,%1,%2,%3};"
        : "+f"(c[0]), "+f"(c[1]), "+f"(c[2]), "+f"(c[3])
        : "r"(a[0]), "r"(a[1]), "r"(a[2]), "r"(a[3]), "r"(b0), "r"(b1));
}

// ---------------- fused prep: blocks [0,8192) convert x, [8192,16384) dequant W ----------------
__global__ __launch_bounds__(256) void prep_kernel(const float* __restrict__ x,
                                                   const int* __restrict__ packed,
                                                   const float* __restrict__ scales,
                                                   const int* __restrict__ zeros) {
    if (blockIdx.x < 8192) {
        // ---- x -> fp16 ----
        size_t i = ((size_t)blockIdx.x * blockDim.x + threadIdx.x) * 8;
        float4 u0 = *(const float4*)(x + i);
        float4 u1 = *(const float4*)(x + i + 4);
        __half2 h0 = __float22half2_rn(make_float2(u0.x, u0.y));
        __half2 h1 = __float22half2_rn(make_float2(u0.z, u0.w));
        __half2 h2 = __float22half2_rn(make_float2(u1.x, u1.y));
        __half2 h3 = __float22half2_rn(make_float2(u1.z, u1.w));
        uint4 o;
        o.x = *(uint32_t*)&h0; o.y = *(uint32_t*)&h1;
        o.z = *(uint32_t*)&h2; o.w = *(uint32_t*)&h3;
        *(uint4*)(g_A + i) = o;
    } else {
        // ---- W = s*(q-z) -> fp16 ----
        // packed[n][j]: one byte per int32, low nibble = weight 2j, high = 2j+1.
        size_t i = ((size_t)(blockIdx.x - 8192) * blockDim.x + threadIdx.x);  // over NF*1024/4
        int4 p = ((const int4*)packed)[i];
        int n  = (int)((i * 4) >> 10);
        int j0 = (int)((i * 4) & 1023);
        int g  = j0 >> 5;
        float s  = scales[n * 32 + g];
        float zs = (float)zeros[n * 32 + g] * s;

        int pp[4] = {p.x, p.y, p.z, p.w};
        uint32_t w[4];
        #pragma unroll
        for (int q = 0; q < 4; q++) {
            float f0 = (float)(pp[q] & 15) * s - zs;
            float f1 = (float)((pp[q] >> 4) & 15) * s - zs;
            __half2 hh = __float22half2_rn(make_float2(f0, f1));
            w[q] = *(uint32_t*)&hh;
        }
        uint4 o; o.x = w[0]; o.y = w[1]; o.z = w[2]; o.w = w[3];
        *(uint4*)(g_B + (size_t)n * NX_DIM + (size_t)j0 * 2) = o;
    }
}

// ---------------- GEMM: D = A @ B^T + bias, single-pass fp16 HMMA ----------------
// 256 threads = 8 warps, warp grid 2(M) x 4(N), warp tile 64x32. 2 CTAs/SM.
// 3-slot pipeline, R14 ordering, single leading sync per iter:
//   iter j: load(j+1) -> slot (j+1)%3 ; wait1 (stage j landed) ; sync ; compute j.
// No trailing barrier: load(j+1) overwrites the slot last read in compute(j-2),
// and the leading sync of iter j-1 already proved compute(j-2) finished globally.
__global__ __launch_bounds__(256, 2)
void gemm_kernel(float* __restrict__ out, const float* __restrict__ bias) {
    extern __shared__ char smem[];
    const uint32_t sb = smem_u32(smem);
    const uint32_t TILE0 = (sb + 1023) & ~1023u;

    const int tid = threadIdx.x;
    const int wid = tid >> 5, lid = tid & 31;
    const int warp_m = wid & 1;
    const int warp_n = wid >> 1;

    const int t  = blockIdx.x;
    const int bm = ((t >> 9) << 3) | (t & 7);   // 8-wide M supertiles: B panel L2-resident
    const int bn = (t >> 3) & 63;

    const char* gA = (const char*)(g_A + (size_t)bm * 128 * NX_DIM);
    const char* gB = (const char*)(g_B + (size_t)bn * 128 * NX_DIM);

    // stage loader: A tile (128 rows x 64 halves = 16KB) + B tile
    auto load_stage = [&](int j, int slot) {
        const uint32_t s0 = TILE0 + slot * STAGE_BYTES;
        #pragma unroll
        for (int i = 0; i < 4; i++) {
            const int c   = tid + i * 256;       // 0..1023: 16B chunk id
            const int row = c >> 3;
            const int seg = c & 7;
            const uint32_t so = SWZ((uint32_t)(row * 128 + seg * 16));
            const size_t go = (size_t)row * (NX_DIM * 2) + (size_t)j * (BK * 2) + seg * 16;
            cpasync16(s0 +         so, gA + go);
            cpasync16(s0 + 16384 + so, gB + go);
        }
        cp_commit();
    };

    float acc[4][4][4];
    #pragma unroll
    for (int a = 0; a < 4; a++)
        #pragma unroll
        for (int b = 0; b < 4; b++)
            #pragma unroll
            for (int c = 0; c < 4; c++) acc[a][b][c] = 0.f;

    // ldmatrix lane addressing (elements)
    const int laneA_row = (lid & 7) + ((lid >> 3) & 1) * 8;
    const int laneA_k8  = ((lid >> 4) & 1) * 8;
    const int laneB_row = (lid & 7) + ((lid >> 4) & 1) * 8;
    const int laneB_k8  = ((lid >> 3) & 1) * 8;

    load_stage(0, 0);

    #pragma unroll 1
    for (int j = 0; j < NITER; j++) {
        if (j + 1 < NITER) { load_stage(j + 1, (j + 1) % NSTAGE); cp_wait1(); }
        else               { cp_wait0(); }
        __syncthreads();

        const uint32_t s0 = TILE0 + (j % NSTAGE) * STAGE_BYTES;
        const uint32_t Ab = s0, Bb = s0 + 16384;

        #pragma unroll
        for (int ks = 0; ks < 4; ks++) {
            uint32_t af[4][4], bf[2][4];
            // issue order: the first MMA's operands (af[0], bf[0], bf[1]) first
            {
                const uint32_t offA0 = SWZ((uint32_t)((warp_m * 64 + laneA_row) * 128
                                                      + (ks * 16 + laneA_k8) * 2));
                ldm4(af[0], Ab + offA0);
            }
            #pragma unroll
            for (int h = 0; h < 2; h++) {
                const uint32_t off = SWZ((uint32_t)((warp_n * 32 + h * 16 + laneB_row) * 128
                                                    + (ks * 16 + laneB_k8) * 2));
                ldm4(bf[h], Bb + off);
            }
            #pragma unroll
            for (int mt = 1; mt < 4; mt++) {
                const uint32_t off = SWZ((uint32_t)((warp_m * 64 + mt * 16 + laneA_row) * 128
                                                    + (ks * 16 + laneA_k8) * 2));
                ldm4(af[mt], Ab + off);
            }
            #pragma unroll
            for (int mt = 0; mt < 4; mt++)
                #pragma unroll
                for (int nt = 0; nt < 4; nt++) {
                    const uint32_t b0 = bf[nt >> 1][(nt & 1) * 2];
                    const uint32_t b1 = bf[nt >> 1][(nt & 1) * 2 + 1];
                    mma16816(acc[mt][nt], af[mt], b0, b1);
                }
        }
    }

    // ---- epilogue: add bias, store fp32 ----
    const int gm0 = bm * 128 + warp_m * 64 + (lid >> 2);
    const int gn0 = bn * 128 + warp_n * 32 + (lid & 3) * 2;
    #pragma unroll
    for (int nt = 0; nt < 4; nt++) {
        const int gn = gn0 + nt * 8;
        const float2 bv = *(const float2*)(bias + gn);
        #pragma unroll
        for (int mt = 0; mt < 4; mt++) {
            const int gm = gm0 + mt * 16;
            float2 v0, v1;
            v0.x = acc[mt][nt][0] + bv.x;  v0.y = acc[mt][nt][1] + bv.y;
            v1.x = acc[mt][nt][2] + bv.x;  v1.y = acc[mt][nt][3] + bv.y;
            *(float2*)(out + (size_t)gm * NF_DIM + gn)       = v0;
            *(float2*)(out + (size_t)(gm + 8) * NF_DIM + gn) = v1;
        }
    }
}

// ---------------- launch ----------------
extern "C" void kernel_launch(void* const* d_in, const int* in_sizes, int n_in,
                              void* d_out, int out_size) {
    const float* x      = (const float*)d_in[0];
    const int*   packed = (const int*)d_in[1];
    const float* scales = (const float*)d_in[2];
    const int*   zeros  = (const int*)d_in[3];
    const float* bias   = (const float*)d_in[4];
    float*       out    = (float*)d_out;

    cudaFuncSetAttribute(gemm_kernel, cudaFuncAttributeMaxDynamicSharedMemorySize, SMEM_BYTES);

    prep_kernel<<<16384, 256>>>(x, packed, scales, zeros);
    gemm_kernel<<<64 * 64, 256, SMEM_BYTES>>>(out, bias);
}